// round 1
// baseline (speedup 1.0000x reference)
#include <cuda_runtime.h>

// Problem constants (from reference):
//  x:    [4, 4096, 2048]  f32   -> M = 16384, K = 2048
//  mask: [4, 4, 4096, 1]  f32   -> mask[n, m]
//  W:    [2048, 2048]     f32   (row-major [N, K])
//  b:    [2048]           f32
//  A:    [4, 16, 2048]    f32   -> A_cat [64, 2048]
//  Bw:   [4, 2048, 16]    f32   -> Bcat[n_out, j] = Bw[j/16, n_out, j%16]
//  out:  [4, 4096, 2048]  f32
#define M_TOTAL 16384
#define K_DIM   2048
#define N_DIM   2048
#define JTOT    64
#define SCALE_F 2.0f

// Scratch for G = (x @ A^T) * SCALE * mask  -> [M_TOTAL, 64]  (4 MB)
__device__ float g_G[M_TOTAL * JTOT];

static __device__ __forceinline__ unsigned long long pack2(float a, float b) {
    unsigned long long r;
    asm("mov.b64 %0, {%1, %2};" : "=l"(r) : "f"(a), "f"(b));
    return r;
}
static __device__ __forceinline__ float2 unpack2(unsigned long long v) {
    float2 r;
    asm("mov.b64 {%0, %1}, %2;" : "=f"(r.x), "=f"(r.y) : "l"(v));
    return r;
}
static __device__ __forceinline__ void ffma2(unsigned long long& d,
                                             unsigned long long a,
                                             unsigned long long b) {
    asm("fma.rn.f32x2 %0, %1, %2, %0;" : "+l"(d) : "l"(a), "l"(b));
}

// ---------------------------------------------------------------------------
// Kernel 1: G[m, j] = (sum_k x[m,k] * A[j,k]) * SCALE * mask[j/16, m]
// Block: 256 threads handles 64 rows (BM=64), all 64 j.  Grid: 256 blocks.
// ---------------------------------------------------------------------------
__global__ __launch_bounds__(256) void lora_g_kernel(
    const float* __restrict__ x,
    const float* __restrict__ A,
    const float* __restrict__ mask)
{
    // k-major planes, padded stride 68 (68 % 32 == 4) to avoid STS conflicts
    __shared__ float xs[32 * 68];  // xs[k][m]
    __shared__ float as[32 * 68];  // as[k][j]

    const int tid = threadIdx.x;
    const int m0  = blockIdx.x * 64;
    const int r   = tid >> 2;          // row within block: 0..63
    const int j0  = (tid & 3) * 16;    // j group: {0,16,32,48}

    unsigned long long acc[8];
#pragma unroll
    for (int p = 0; p < 8; p++) acc[p] = 0ULL;

    for (int k0 = 0; k0 < K_DIM; k0 += 32) {
#pragma unroll
        for (int q = 0; q < 2; q++) {
            int idx = tid + q * 256;       // 0..511
            int mm  = idx >> 3;            // 0..63
            int k   = (idx & 7) * 4;       // 0,4,..,28
            float4 xv = *(const float4*)(x + (size_t)(m0 + mm) * K_DIM + k0 + k);
            xs[(k + 0) * 68 + mm] = xv.x;
            xs[(k + 1) * 68 + mm] = xv.y;
            xs[(k + 2) * 68 + mm] = xv.z;
            xs[(k + 3) * 68 + mm] = xv.w;
            float4 av = *(const float4*)(A + (size_t)mm * K_DIM + k0 + k);
            as[(k + 0) * 68 + mm] = av.x;
            as[(k + 1) * 68 + mm] = av.y;
            as[(k + 2) * 68 + mm] = av.z;
            as[(k + 3) * 68 + mm] = av.w;
        }
        __syncthreads();
#pragma unroll
        for (int k = 0; k < 32; k++) {
            float xv = xs[k * 68 + r];
            unsigned long long xp = pack2(xv, xv);
            const unsigned long long* a2 =
                (const unsigned long long*)(as + k * 68 + j0);
#pragma unroll
            for (int p = 0; p < 8; p++) ffma2(acc[p], xp, a2[p]);
        }
        __syncthreads();
    }

    const int n_ad = tid & 3;  // adaptor index = j0 / 16
    const float mval = mask[(size_t)n_ad * M_TOTAL + (m0 + r)] * SCALE_F;
    float* gout = g_G + (size_t)(m0 + r) * JTOT + j0;
#pragma unroll
    for (int p = 0; p < 8; p++) {
        float2 v = unpack2(acc[p]);
        v.x *= mval;
        v.y *= mval;
        *(float2*)(gout + 2 * p) = v;
    }
}

// ---------------------------------------------------------------------------
// Kernel 2: out = x @ W^T + G @ Bcat^T + b
// Tiles: BM=128, BN=128, BK=16.  256 threads, 8x8 per-thread tile.
// K-loop: 128 iterations over x/W, then 4 iterations over G/Bw (one per
// adaptor) reusing identical smem layout and inner loop.
// ---------------------------------------------------------------------------
__global__ __launch_bounds__(256, 2) void main_gemm_kernel(
    const float* __restrict__ x,
    const float* __restrict__ W,
    const float* __restrict__ bias,
    const float* __restrict__ Bw,
    float* __restrict__ out)
{
    // k-major planes, padded stride 132 (132 % 32 == 4)
    __shared__ float a_s[16 * 132];  // a_s[k][m]
    __shared__ float b_s[16 * 132];  // b_s[k][n]

    const int tid = threadIdx.x;
    const int n0  = blockIdx.x * 128;
    const int m0  = blockIdx.y * 128;
    const int tm  = tid >> 4;   // 0..15 -> rows tm*8 .. tm*8+7
    const int tn  = tid & 15;   // 0..15 -> cols tn*8 .. tn*8+7

    unsigned long long acc[8][4];
#pragma unroll
    for (int i = 0; i < 8; i++)
#pragma unroll
        for (int p = 0; p < 4; p++) acc[i][p] = 0ULL;

    for (int t = 0; t < 132; t++) {
#pragma unroll
        for (int q = 0; q < 2; q++) {
            int idx = tid + q * 256;   // 0..511
            int row = idx >> 2;        // 0..127
            int k   = (idx & 3) * 4;   // 0,4,8,12
            const float* pa;
            const float* pb;
            if (t < 128) {
                pa = x + (size_t)(m0 + row) * K_DIM + t * 16 + k;
                pb = W + (size_t)(n0 + row) * K_DIM + t * 16 + k;
            } else {
                int na = t - 128;      // adaptor index
                pa = g_G + (size_t)(m0 + row) * JTOT + na * 16 + k;
                pb = Bw + (size_t)na * (N_DIM * 16) + (size_t)(n0 + row) * 16 + k;
            }
            float4 av = *(const float4*)pa;
            float4 bv = *(const float4*)pb;
            a_s[(k + 0) * 132 + row] = av.x;
            a_s[(k + 1) * 132 + row] = av.y;
            a_s[(k + 2) * 132 + row] = av.z;
            a_s[(k + 3) * 132 + row] = av.w;
            b_s[(k + 0) * 132 + row] = bv.x;
            b_s[(k + 1) * 132 + row] = bv.y;
            b_s[(k + 2) * 132 + row] = bv.z;
            b_s[(k + 3) * 132 + row] = bv.w;
        }
        __syncthreads();
#pragma unroll
        for (int k = 0; k < 16; k++) {
            const float* ap = a_s + k * 132 + tm * 8;
            float4 a0 = *(const float4*)ap;
            float4 a1 = *(const float4*)(ap + 4);
            const ulonglong2* bp2 = (const ulonglong2*)(b_s + k * 132 + tn * 8);
            ulonglong2 q0 = bp2[0];
            ulonglong2 q1 = bp2[1];
            unsigned long long bp[4] = {q0.x, q0.y, q1.x, q1.y};
            float am[8] = {a0.x, a0.y, a0.z, a0.w, a1.x, a1.y, a1.z, a1.w};
#pragma unroll
            for (int i = 0; i < 8; i++) {
                unsigned long long ai = pack2(am[i], am[i]);
#pragma unroll
                for (int p = 0; p < 4; p++) ffma2(acc[i][p], ai, bp[p]);
            }
        }
        __syncthreads();
    }

    float bias8[8];
#pragma unroll
    for (int j = 0; j < 8; j++) bias8[j] = bias[n0 + tn * 8 + j];

#pragma unroll
    for (int i = 0; i < 8; i++) {
        float* po = out + (size_t)(m0 + tm * 8 + i) * N_DIM + n0 + tn * 8;
#pragma unroll
        for (int h = 0; h < 2; h++) {
            float2 v0 = unpack2(acc[i][2 * h]);
            float2 v1 = unpack2(acc[i][2 * h + 1]);
            float4 w4 = make_float4(v0.x + bias8[4 * h + 0],
                                    v0.y + bias8[4 * h + 1],
                                    v1.x + bias8[4 * h + 2],
                                    v1.y + bias8[4 * h + 3]);
            *(float4*)(po + 4 * h) = w4;
        }
    }
}

extern "C" void kernel_launch(void* const* d_in, const int* in_sizes, int n_in,
                              void* d_out, int out_size)
{
    const float* x    = (const float*)d_in[0];
    const float* mask = (const float*)d_in[1];
    const float* W    = (const float*)d_in[2];
    const float* b    = (const float*)d_in[3];
    const float* A    = (const float*)d_in[4];
    const float* Bw   = (const float*)d_in[5];
    float* out        = (float*)d_out;

    lora_g_kernel<<<M_TOTAL / 64, 256>>>(x, A, mask);

    dim3 grid(N_DIM / 128, M_TOTAL / 128);
    main_gemm_kernel<<<grid, 256>>>(x, W, b, Bw, out);
}

// round 3
// speedup vs baseline: 3.2837x; 3.2837x over previous
#include <cuda_runtime.h>
#include <cuda_bf16.h>
#include <cstdint>

// Shapes: x[16384,2048] f32, mask[4,16384], W[2048,2048], b[2048],
//         A[4,16,2048] -> Acat[64,2048] (contiguous reshape), Bw[4,2048,16]
#define M_TOTAL 16384
#define K_DIM   2048
#define N_DIM   2048
#define JTOT    64
#define SCALE_F 2.0f

// ---------------- device scratch ------------------------------------------
__device__ __align__(16) __nv_bfloat16 g_xh[(size_t)M_TOTAL * K_DIM];
__device__ __align__(16) __nv_bfloat16 g_xl[(size_t)M_TOTAL * K_DIM];
__device__ __align__(16) __nv_bfloat16 g_wh[(size_t)N_DIM * K_DIM];
__device__ __align__(16) __nv_bfloat16 g_wl[(size_t)N_DIM * K_DIM];
__device__ __align__(16) __nv_bfloat16 g_ah[(size_t)JTOT * K_DIM];
__device__ __align__(16) __nv_bfloat16 g_al[(size_t)JTOT * K_DIM];
__device__ __align__(16) __nv_bfloat16 g_gh[(size_t)M_TOTAL * JTOT];
__device__ __align__(16) __nv_bfloat16 g_gl[(size_t)M_TOTAL * JTOT];
__device__ __align__(16) __nv_bfloat16 g_bh[(size_t)N_DIM * JTOT];
__device__ __align__(16) __nv_bfloat16 g_bl[(size_t)N_DIM * JTOT];

// ---------------- helpers --------------------------------------------------
static __device__ __forceinline__ uint32_t smem_u32(const void* p) {
    uint32_t a;
    asm("{ .reg .u64 t; cvta.to.shared.u64 t, %1; cvt.u32.u64 %0, t; }"
        : "=r"(a) : "l"(p));
    return a;
}
// bf16x2(a,b) = {lo=a, hi=b}
static __device__ __forceinline__ uint32_t bf16x2(float a, float b) {
    uint32_t r;
    asm("cvt.rn.bf16x2.f32 %0, %1, %2;" : "=r"(r) : "f"(b), "f"(a));
    return r;
}
static __device__ __forceinline__ void cpasync16(uint32_t dst, const void* src) {
    asm volatile("cp.async.cg.shared.global [%0], [%1], 16;"
                 :: "r"(dst), "l"(src) : "memory");
}
#define CP_COMMIT() asm volatile("cp.async.commit_group;" ::: "memory")
#define CP_WAIT2()  asm volatile("cp.async.wait_group 2;" ::: "memory")

#define LDSM4(r, addr)                                                       \
    asm volatile("ldmatrix.sync.aligned.m8n8.x4.shared.b16 {%0,%1,%2,%3}, [%4];" \
        : "=r"((r)[0]), "=r"((r)[1]), "=r"((r)[2]), "=r"((r)[3]) : "r"(addr))

#define MMA16816(c, a, b)                                                    \
    asm volatile(                                                            \
        "mma.sync.aligned.m16n8k16.row.col.f32.bf16.bf16.f32 "               \
        "{%0,%1,%2,%3}, {%4,%5,%6,%7}, {%8,%9}, {%0,%1,%2,%3};"              \
        : "+f"((c)[0]), "+f"((c)[1]), "+f"((c)[2]), "+f"((c)[3])             \
        : "r"((a)[0]), "r"((a)[1]), "r"((a)[2]), "r"((a)[3]),                \
          "r"((b)[0]), "r"((b)[1]))

// Swizzled smem offset: 64B rows (BK=32 bf16), 4 chunks of 16B per row.
static __device__ __forceinline__ uint32_t sw_off(int row, int chunk) {
    return (uint32_t)(row * 64 + ((chunk ^ ((row >> 1) & 3)) << 4));
}

// ---------------- split conversion kernels --------------------------------
static __device__ __forceinline__ void split4(float4 v, uint2& h, uint2& l) {
    h.x = bf16x2(v.x, v.y);
    h.y = bf16x2(v.z, v.w);
    float r0 = v.x - __uint_as_float(h.x << 16);
    float r1 = v.y - __uint_as_float(h.x & 0xffff0000u);
    float r2 = v.z - __uint_as_float(h.y << 16);
    float r3 = v.w - __uint_as_float(h.y & 0xffff0000u);
    l.x = bf16x2(r0, r1);
    l.y = bf16x2(r2, r3);
}
__global__ void split_x_kernel(const float* __restrict__ src, int n4) {
    int i = blockIdx.x * blockDim.x + threadIdx.x;
    if (i >= n4) return;
    float4 v = ((const float4*)src)[i];
    uint2 h, l;
    split4(v, h, l);
    ((uint2*)g_xh)[i] = h;
    ((uint2*)g_xl)[i] = l;
}
__global__ void split_w_kernel(const float* __restrict__ src, int n4) {
    int i = blockIdx.x * blockDim.x + threadIdx.x;
    if (i >= n4) return;
    float4 v = ((const float4*)src)[i];
    uint2 h, l;
    split4(v, h, l);
    ((uint2*)g_wh)[i] = h;
    ((uint2*)g_wl)[i] = l;
}
__global__ void split_a_kernel(const float* __restrict__ src, int n4) {
    int i = blockIdx.x * blockDim.x + threadIdx.x;
    if (i >= n4) return;
    float4 v = ((const float4*)src)[i];
    uint2 h, l;
    split4(v, h, l);
    ((uint2*)g_ah)[i] = h;
    ((uint2*)g_al)[i] = l;
}
// Bcat[n, na*16+r] = Bw[na, n, r]
__global__ void conv_b_kernel(const float* __restrict__ Bw) {
    int idx = blockIdx.x * blockDim.x + threadIdx.x;
    int na = idx >> 15;
    int n  = (idx >> 4) & 2047;
    int r  = idx & 15;
    float v = Bw[idx];
    __nv_bfloat16 h = __float2bfloat16(v);
    __nv_bfloat16 lo = __float2bfloat16(v - __bfloat162float(h));
    size_t dst = (size_t)n * JTOT + na * 16 + r;
    g_bh[dst] = h;
    g_bl[dst] = lo;
}

// ---------------- G kernel: G = (x @ Acat^T) * SCALE * mask ---------------
// BM=128, BN=64, BK=32.  256 thr, warps 2x4: warp tile 64x16.
#define G_STAGE  24576   // AH 8K + AL 8K + BH 4K + BL 4K
#define G_SMEM   (4 * G_STAGE)

__global__ __launch_bounds__(256, 1) void g_gemm_kernel(
    const float* __restrict__ mask)
{
    extern __shared__ __align__(128) char smem[];
    const uint32_t sb = smem_u32(smem);
    const int tid = threadIdx.x, wid = tid >> 5, lane = tid & 31;
    const int warp_m = wid >> 2, warp_n = wid & 3;
    const int m0 = blockIdx.x * 128;

    float acc[4][2][4];
#pragma unroll
    for (int i = 0; i < 4; i++)
#pragma unroll
        for (int j = 0; j < 2; j++)
#pragma unroll
            for (int p = 0; p < 4; p++) acc[i][j][p] = 0.f;

    auto load_stage = [&](int c, int st_i) {
        uint32_t st = sb + (uint32_t)st_i * G_STAGE;
        const __nv_bfloat16* axh = g_xh + (size_t)m0 * K_DIM + c * 32;
        const __nv_bfloat16* axl = g_xl + (size_t)m0 * K_DIM + c * 32;
        const __nv_bfloat16* bah = g_ah + (size_t)c * 32;
        const __nv_bfloat16* bal = g_al + (size_t)c * 32;
#pragma unroll
        for (int q = 0; q < 2; q++) {
            int idx = tid + q * 256;
            int m = idx >> 2, ch = idx & 3;
            uint32_t so = sw_off(m, ch);
            size_t go = (size_t)m * K_DIM + ch * 8;
            cpasync16(st + so, axh + go);
            cpasync16(st + 8192 + so, axl + go);
        }
        {
            int n = tid >> 2, ch = tid & 3;
            uint32_t so = sw_off(n, ch);
            size_t go = (size_t)n * K_DIM + ch * 8;
            cpasync16(st + 16384 + so, bah + go);
            cpasync16(st + 20480 + so, bal + go);
        }
    };

    load_stage(0, 0); CP_COMMIT();
    load_stage(1, 1); CP_COMMIT();
    load_stage(2, 2); CP_COMMIT();

    for (int c = 0; c < 64; c++) {
        CP_WAIT2();
        __syncthreads();
        if (c + 3 < 64) load_stage(c + 3, (c + 3) & 3);
        CP_COMMIT();

        uint32_t st = sb + (uint32_t)(c & 3) * G_STAGE;
#pragma unroll
        for (int s = 0; s < 2; s++) {
            uint32_t ah[4][4], al[4][4], bh[4], bl[4];
#pragma unroll
            for (int mi = 0; mi < 4; mi++) {
                int row = warp_m * 64 + mi * 16 + (lane & 15);
                int ch = s * 2 + (lane >> 4);
                uint32_t ad = st + sw_off(row, ch);
                LDSM4(ah[mi], ad);
                LDSM4(al[mi], ad + 8192);
            }
            {
                int nrow = warp_n * 16 + ((lane >> 4) << 3) + (lane & 7);
                int ch = s * 2 + ((lane >> 3) & 1);
                uint32_t ad = st + 16384 + sw_off(nrow, ch);
                LDSM4(bh, ad);
                LDSM4(bl, ad + 4096);
            }
#pragma unroll
            for (int mi = 0; mi < 4; mi++)
#pragma unroll
                for (int nt = 0; nt < 2; nt++) {
                    const uint32_t* ph = bh + nt * 2;
                    const uint32_t* pl = bl + nt * 2;
                    MMA16816(acc[mi][nt], ah[mi], ph);
                    MMA16816(acc[mi][nt], ah[mi], pl);
                    MMA16816(acc[mi][nt], al[mi], ph);
                }
        }
    }

    // epilogue: scale by SCALE*mask[warp_n][m], split to bf16 hi/lo
#pragma unroll
    for (int mi = 0; mi < 4; mi++)
#pragma unroll
        for (int h = 0; h < 2; h++) {
            int m = m0 + warp_m * 64 + mi * 16 + (lane >> 2) + h * 8;
            float mv = mask[(size_t)warp_n * M_TOTAL + m] * SCALE_F;
#pragma unroll
            for (int nt = 0; nt < 2; nt++) {
                float v0 = acc[mi][nt][2 * h + 0] * mv;
                float v1 = acc[mi][nt][2 * h + 1] * mv;
                uint32_t hh = bf16x2(v0, v1);
                float r0 = v0 - __uint_as_float(hh << 16);
                float r1 = v1 - __uint_as_float(hh & 0xffff0000u);
                uint32_t ll = bf16x2(r0, r1);
                size_t off = (size_t)m * JTOT + warp_n * 16 + nt * 8 + (lane & 3) * 2;
                *(uint32_t*)(g_gh + off) = hh;
                *(uint32_t*)(g_gl + off) = ll;
            }
        }
}

// ---------------- main fused GEMM -----------------------------------------
// out = x@W^T + G@Bcat^T + b.  BM=BN=128, BK=32, 66 K-chunks (64 + 2 LoRA).
#define MSTAGE 32768     // AH 8K, AL 8K, BH 8K, BL 8K
#define MAIN_SMEM (4 * MSTAGE)
#define NCHUNK 66

__global__ __launch_bounds__(256, 1) void main_gemm_kernel(
    const float* __restrict__ bias, float* __restrict__ out)
{
    extern __shared__ __align__(128) char smem[];
    const uint32_t sb = smem_u32(smem);
    const int tid = threadIdx.x, wid = tid >> 5, lane = tid & 31;
    const int warp_m = wid >> 2, warp_n = wid & 3;
    const int n0 = blockIdx.x * 128, m0 = blockIdx.y * 128;

    float acc[4][4][4];
#pragma unroll
    for (int i = 0; i < 4; i++)
#pragma unroll
        for (int j = 0; j < 4; j++)
#pragma unroll
            for (int p = 0; p < 4; p++) acc[i][j][p] = 0.f;

    auto load_stage = [&](int c, int st_i) {
        uint32_t st = sb + (uint32_t)st_i * MSTAGE;
        const __nv_bfloat16 *pah, *pal, *pbh, *pbl;
        size_t strd;
        if (c < 64) {
            size_t ka = (size_t)m0 * K_DIM + c * 32;
            size_t kb = (size_t)n0 * K_DIM + c * 32;
            pah = g_xh + ka; pal = g_xl + ka;
            pbh = g_wh + kb; pbl = g_wl + kb;
            strd = K_DIM;
        } else {
            size_t ka = (size_t)m0 * JTOT + (c - 64) * 32;
            size_t kb = (size_t)n0 * JTOT + (c - 64) * 32;
            pah = g_gh + ka; pal = g_gl + ka;
            pbh = g_bh + kb; pbl = g_bl + kb;
            strd = JTOT;
        }
#pragma unroll
        for (int q = 0; q < 2; q++) {
            int idx = tid + q * 256;
            int r = idx >> 2, ch = idx & 3;
            uint32_t so = sw_off(r, ch);
            size_t go = (size_t)r * strd + ch * 8;
            cpasync16(st + so, pah + go);
            cpasync16(st + 8192 + so, pal + go);
            cpasync16(st + 16384 + so, pbh + go);
            cpasync16(st + 24576 + so, pbl + go);
        }
    };

    load_stage(0, 0); CP_COMMIT();
    load_stage(1, 1); CP_COMMIT();
    load_stage(2, 2); CP_COMMIT();

    for (int c = 0; c < NCHUNK; c++) {
        CP_WAIT2();
        __syncthreads();
        if (c + 3 < NCHUNK) load_stage(c + 3, (c + 3) & 3);
        CP_COMMIT();

        uint32_t st = sb + (uint32_t)(c & 3) * MSTAGE;
#pragma unroll
        for (int s = 0; s < 2; s++) {
            uint32_t ah[4][4], al[4][4], bh[2][4], bl[2][4];
#pragma unroll
            for (int mi = 0; mi < 4; mi++) {
                int row = warp_m * 64 + mi * 16 + (lane & 15);
                int ch = s * 2 + (lane >> 4);
                uint32_t ad = st + sw_off(row, ch);
                LDSM4(ah[mi], ad);
                LDSM4(al[mi], ad + 8192);
            }
#pragma unroll
            for (int bj = 0; bj < 2; bj++) {
                int nrow = warp_n * 32 + bj * 16 + ((lane >> 4) << 3) + (lane & 7);
                int ch = s * 2 + ((lane >> 3) & 1);
                uint32_t ad = st + 16384 + sw_off(nrow, ch);
                LDSM4(bh[bj], ad);
                LDSM4(bl[bj], ad + 8192);
            }
#pragma unroll
            for (int mi = 0; mi < 4; mi++)
#pragma unroll
                for (int nt = 0; nt < 4; nt++) {
                    const uint32_t* ph = bh[nt >> 1] + (nt & 1) * 2;
                    const uint32_t* pl = bl[nt >> 1] + (nt & 1) * 2;
                    MMA16816(acc[mi][nt], ah[mi], ph);
                    MMA16816(acc[mi][nt], ah[mi], pl);
                    MMA16816(acc[mi][nt], al[mi], ph);
                }
        }
    }

    // epilogue: + bias, fp32 out
    float2 bfrag[4];
#pragma unroll
    for (int nt = 0; nt < 4; nt++)
        bfrag[nt] = *(const float2*)(bias + n0 + warp_n * 32 + nt * 8 + (lane & 3) * 2);

#pragma unroll
    for (int mi = 0; mi < 4; mi++)
#pragma unroll
        for (int h = 0; h < 2; h++) {
            int m = m0 + warp_m * 64 + mi * 16 + (lane >> 2) + h * 8;
            float* po = out + (size_t)m * N_DIM + n0 + warp_n * 32;
#pragma unroll
            for (int nt = 0; nt < 4; nt++) {
                float2 v;
                v.x = acc[mi][nt][2 * h + 0] + bfrag[nt].x;
                v.y = acc[mi][nt][2 * h + 1] + bfrag[nt].y;
                *(float2*)(po + nt * 8 + (lane & 3) * 2) = v;
            }
        }
}

// ---------------------------------------------------------------------------
extern "C" void kernel_launch(void* const* d_in, const int* in_sizes, int n_in,
                              void* d_out, int out_size)
{
    const float* x    = (const float*)d_in[0];
    const float* mask = (const float*)d_in[1];
    const float* W    = (const float*)d_in[2];
    const float* b    = (const float*)d_in[3];
    const float* A    = (const float*)d_in[4];
    const float* Bw   = (const float*)d_in[5];
    float* out        = (float*)d_out;

    cudaFuncSetAttribute(g_gemm_kernel,
                         cudaFuncAttributeMaxDynamicSharedMemorySize, G_SMEM);
    cudaFuncSetAttribute(main_gemm_kernel,
                         cudaFuncAttributeMaxDynamicSharedMemorySize, MAIN_SMEM);

    int n4x = (M_TOTAL * K_DIM) / 4;
    split_x_kernel<<<n4x / 256, 256>>>(x, n4x);
    int n4w = (N_DIM * K_DIM) / 4;
    split_w_kernel<<<n4w / 256, 256>>>(W, n4w);
    int n4a = (JTOT * K_DIM) / 4;
    split_a_kernel<<<(n4a + 255) / 256, 256>>>(A, n4a);
    conv_b_kernel<<<(4 * 2048 * 16) / 256, 256>>>(Bw);

    g_gemm_kernel<<<M_TOTAL / 128, 256, G_SMEM>>>(mask);

    dim3 grid(N_DIM / 128, M_TOTAL / 128);
    main_gemm_kernel<<<grid, 256, MAIN_SMEM>>>(b, out);
}

// round 4
// speedup vs baseline: 3.5957x; 1.0950x over previous
#include <cuda_runtime.h>
#include <cuda_fp16.h>
#include <cstdint>

// Shapes: x[16384,2048] f32, mask[4,16384], W[2048,2048], b[2048],
//         A[4,16,2048] -> Acat[64,2048], Bw[4,2048,16] -> Bcat[2048,64]
#define M_TOTAL 16384
#define K_DIM   2048
#define N_DIM   2048
#define JTOT    64
#define SCALE_F 2.0f

// ---------------- device scratch ------------------------------------------
__device__ __align__(16) __half g_xh[(size_t)M_TOTAL * K_DIM];   // x, 1 term
__device__ __align__(16) __half g_wh[(size_t)N_DIM * K_DIM];     // W hi
__device__ __align__(16) __half g_wl[(size_t)N_DIM * K_DIM];     // W lo
__device__ __align__(16) __half g_ah[(size_t)JTOT * K_DIM];      // Acat hi
__device__ __align__(16) __half g_al[(size_t)JTOT * K_DIM];      // Acat lo
__device__ __align__(16) __half g_g [(size_t)M_TOTAL * JTOT];    // G, 1 term
__device__ __align__(16) __half g_bh[(size_t)N_DIM * JTOT];      // Bcat hi
__device__ __align__(16) __half g_bl[(size_t)N_DIM * JTOT];      // Bcat lo

// ---------------- helpers --------------------------------------------------
static __device__ __forceinline__ uint32_t smem_u32(const void* p) {
    uint32_t a;
    asm("{ .reg .u64 t; cvta.to.shared.u64 t, %1; cvt.u32.u64 %0, t; }"
        : "=r"(a) : "l"(p));
    return a;
}
// pack two floats into f16x2 {lo=a, hi=b}
static __device__ __forceinline__ uint32_t f16x2(float a, float b) {
    uint32_t r;
    asm("cvt.rn.f16x2.f32 %0, %1, %2;" : "=r"(r) : "f"(b), "f"(a));
    return r;
}
static __device__ __forceinline__ void cpasync16(uint32_t dst, const void* src) {
    asm volatile("cp.async.cg.shared.global [%0], [%1], 16;"
                 :: "r"(dst), "l"(src) : "memory");
}
#define CP_COMMIT() asm volatile("cp.async.commit_group;" ::: "memory")
#define CP_WAIT2()  asm volatile("cp.async.wait_group 2;" ::: "memory")

#define LDSM4(r, addr)                                                       \
    asm volatile("ldmatrix.sync.aligned.m8n8.x4.shared.b16 {%0,%1,%2,%3}, [%4];" \
        : "=r"((r)[0]), "=r"((r)[1]), "=r"((r)[2]), "=r"((r)[3]) : "r"(addr))

#define MMA16816(c, a, b)                                                    \
    asm volatile(                                                            \
        "mma.sync.aligned.m16n8k16.row.col.f32.f16.f16.f32 "                 \
        "{%0,%1,%2,%3}, {%4,%5,%6,%7}, {%8,%9}, {%0,%1,%2,%3};"              \
        : "+f"((c)[0]), "+f"((c)[1]), "+f"((c)[2]), "+f"((c)[3])             \
        : "r"((a)[0]), "r"((a)[1]), "r"((a)[2]), "r"((a)[3]),                \
          "r"((b)[0]), "r"((b)[1]))

// Swizzled smem offset: 64B rows (BK=32 halves), 4 chunks of 16B per row.
static __device__ __forceinline__ uint32_t sw_off(int row, int chunk) {
    return (uint32_t)(row * 64 + ((chunk ^ ((row >> 1) & 3)) << 4));
}

// ---------------- conversion kernels --------------------------------------
__global__ void conv_x_kernel(const float* __restrict__ src, int n4) {
    int i = blockIdx.x * blockDim.x + threadIdx.x;
    if (i >= n4) return;
    float4 v = ((const float4*)src)[i];
    uint2 h;
    h.x = f16x2(v.x, v.y);
    h.y = f16x2(v.z, v.w);
    ((uint2*)g_xh)[i] = h;
}
static __device__ __forceinline__ void split4h(float4 v, uint2& h, uint2& l) {
    __half h0 = __float2half_rn(v.x), h1 = __float2half_rn(v.y);
    __half h2 = __float2half_rn(v.z), h3 = __float2half_rn(v.w);
    h.x = ((uint32_t)__half_as_ushort(h1) << 16) | __half_as_ushort(h0);
    h.y = ((uint32_t)__half_as_ushort(h3) << 16) | __half_as_ushort(h2);
    l.x = f16x2(v.x - __half2float(h0), v.y - __half2float(h1));
    l.y = f16x2(v.z - __half2float(h2), v.w - __half2float(h3));
}
__global__ void split_w_kernel(const float* __restrict__ src, int n4) {
    int i = blockIdx.x * blockDim.x + threadIdx.x;
    if (i >= n4) return;
    float4 v = ((const float4*)src)[i];
    uint2 h, l;
    split4h(v, h, l);
    ((uint2*)g_wh)[i] = h;
    ((uint2*)g_wl)[i] = l;
}
__global__ void split_a_kernel(const float* __restrict__ src, int n4) {
    int i = blockIdx.x * blockDim.x + threadIdx.x;
    if (i >= n4) return;
    float4 v = ((const float4*)src)[i];
    uint2 h, l;
    split4h(v, h, l);
    ((uint2*)g_ah)[i] = h;
    ((uint2*)g_al)[i] = l;
}
// Bcat[n, na*16+r] = Bw[na, n, r]; fp16 hi/lo
__global__ void conv_b_kernel(const float* __restrict__ Bw) {
    int idx = blockIdx.x * blockDim.x + threadIdx.x;
    int na = idx >> 15;
    int n  = (idx >> 4) & 2047;
    int r  = idx & 15;
    float v = Bw[idx];
    __half h = __float2half_rn(v);
    __half lo = __float2half_rn(v - __half2float(h));
    size_t dst = (size_t)n * JTOT + na * 16 + r;
    g_bh[dst] = h;
    g_bl[dst] = lo;
}

// ---------------- G kernel: G = (x @ Acat^T) * SCALE * mask ---------------
// BM=128, BN=64, BK=32.  256 thr, warps 2x4: warp tile 64x16.
// Planes: X 8K @0, AH 4K @8192, AL 4K @12288.  Stage 16K, 4 stages.
#define G_STAGE  16384
#define G_SMEM   (4 * G_STAGE)

__global__ __launch_bounds__(256, 2) void g_gemm_kernel(
    const float* __restrict__ mask)
{
    extern __shared__ __align__(128) char smem[];
    const uint32_t sb = smem_u32(smem);
    const int tid = threadIdx.x, wid = tid >> 5, lane = tid & 31;
    const int warp_m = wid >> 2, warp_n = wid & 3;
    const int m0 = blockIdx.x * 128;

    float acc[4][2][4];
#pragma unroll
    for (int i = 0; i < 4; i++)
#pragma unroll
        for (int j = 0; j < 2; j++)
#pragma unroll
            for (int p = 0; p < 4; p++) acc[i][j][p] = 0.f;

    auto load_stage = [&](int c, int st_i) {
        uint32_t st = sb + (uint32_t)st_i * G_STAGE;
        const __half* px  = g_xh + (size_t)m0 * K_DIM + c * 32;
        const __half* pah = g_ah + (size_t)c * 32;
        const __half* pal = g_al + (size_t)c * 32;
#pragma unroll
        for (int q = 0; q < 2; q++) {
            int idx = tid + q * 256;
            int m = idx >> 2, ch = idx & 3;
            cpasync16(st + sw_off(m, ch), px + (size_t)m * K_DIM + ch * 8);
        }
        {
            int n = tid >> 2, ch = tid & 3;
            uint32_t so = sw_off(n, ch);
            size_t go = (size_t)n * K_DIM + ch * 8;
            cpasync16(st + 8192 + so, pah + go);
            cpasync16(st + 12288 + so, pal + go);
        }
    };

    load_stage(0, 0); CP_COMMIT();
    load_stage(1, 1); CP_COMMIT();
    load_stage(2, 2); CP_COMMIT();

    for (int c = 0; c < 64; c++) {
        CP_WAIT2();
        __syncthreads();
        if (c + 3 < 64) load_stage(c + 3, (c + 3) & 3);
        CP_COMMIT();

        uint32_t st = sb + (uint32_t)(c & 3) * G_STAGE;
#pragma unroll
        for (int s = 0; s < 2; s++) {
            uint32_t xa[4][4], bh[4], bl[4];
#pragma unroll
            for (int mi = 0; mi < 4; mi++) {
                int row = warp_m * 64 + mi * 16 + (lane & 15);
                int ch = s * 2 + (lane >> 4);
                LDSM4(xa[mi], st + sw_off(row, ch));
            }
            {
                int nrow = warp_n * 16 + ((lane >> 4) << 3) + (lane & 7);
                int ch = s * 2 + ((lane >> 3) & 1);
                uint32_t ad = st + 8192 + sw_off(nrow, ch);
                LDSM4(bh, ad);
                LDSM4(bl, ad + 4096);
            }
#pragma unroll
            for (int mi = 0; mi < 4; mi++)
#pragma unroll
                for (int nt = 0; nt < 2; nt++) {
                    MMA16816(acc[mi][nt], xa[mi], bh + nt * 2);
                    MMA16816(acc[mi][nt], xa[mi], bl + nt * 2);
                }
        }
    }

    // epilogue: scale by SCALE*mask[warp_n][m], fp16 single-plane out
#pragma unroll
    for (int mi = 0; mi < 4; mi++)
#pragma unroll
        for (int h = 0; h < 2; h++) {
            int m = m0 + warp_m * 64 + mi * 16 + (lane >> 2) + h * 8;
            float mv = mask[(size_t)warp_n * M_TOTAL + m] * SCALE_F;
#pragma unroll
            for (int nt = 0; nt < 2; nt++) {
                float v0 = acc[mi][nt][2 * h + 0] * mv;
                float v1 = acc[mi][nt][2 * h + 1] * mv;
                size_t off = (size_t)m * JTOT + warp_n * 16 + nt * 8 + (lane & 3) * 2;
                *(uint32_t*)(g_g + off) = f16x2(v0, v1);
            }
        }
}

// ---------------- main fused GEMM -----------------------------------------
// out = x@W^T + G@Bcat^T + b.  BM=BN=128, BK=32, 66 K-chunks (64 + 2 LoRA).
// Planes: A 8K @0, BH 8K @8192, BL 8K @16384.  Stage 24K, 4 stages = 96K.
#define MSTAGE 24576
#define MAIN_SMEM (4 * MSTAGE)
#define NCHUNK 66

__global__ __launch_bounds__(256, 2) void main_gemm_kernel(
    const float* __restrict__ bias, float* __restrict__ out)
{
    extern __shared__ __align__(128) char smem[];
    const uint32_t sb = smem_u32(smem);
    const int tid = threadIdx.x, wid = tid >> 5, lane = tid & 31;
    const int warp_m = wid >> 2, warp_n = wid & 3;
    const int n0 = blockIdx.x * 128, m0 = blockIdx.y * 128;

    float acc[4][4][4];
#pragma unroll
    for (int i = 0; i < 4; i++)
#pragma unroll
        for (int j = 0; j < 4; j++)
#pragma unroll
            for (int p = 0; p < 4; p++) acc[i][j][p] = 0.f;

    auto load_stage = [&](int c, int st_i) {
        uint32_t st = sb + (uint32_t)st_i * MSTAGE;
        const __half *pa, *pbh, *pbl;
        size_t strd;
        if (c < 64) {
            pa  = g_xh + (size_t)m0 * K_DIM + c * 32;
            pbh = g_wh + (size_t)n0 * K_DIM + c * 32;
            pbl = g_wl + (size_t)n0 * K_DIM + c * 32;
            strd = K_DIM;
        } else {
            pa  = g_g  + (size_t)m0 * JTOT + (c - 64) * 32;
            pbh = g_bh + (size_t)n0 * JTOT + (c - 64) * 32;
            pbl = g_bl + (size_t)n0 * JTOT + (c - 64) * 32;
            strd = JTOT;
        }
#pragma unroll
        for (int q = 0; q < 2; q++) {
            int idx = tid + q * 256;
            int r = idx >> 2, ch = idx & 3;
            uint32_t so = sw_off(r, ch);
            size_t go = (size_t)r * strd + ch * 8;
            cpasync16(st + so, pa + go);
            cpasync16(st + 8192 + so, pbh + go);
            cpasync16(st + 16384 + so, pbl + go);
        }
    };

    load_stage(0, 0); CP_COMMIT();
    load_stage(1, 1); CP_COMMIT();
    load_stage(2, 2); CP_COMMIT();

    for (int c = 0; c < NCHUNK; c++) {
        CP_WAIT2();
        __syncthreads();
        if (c + 3 < NCHUNK) load_stage(c + 3, (c + 3) & 3);
        CP_COMMIT();

        uint32_t st = sb + (uint32_t)(c & 3) * MSTAGE;
#pragma unroll
        for (int s = 0; s < 2; s++) {
            uint32_t ah[4][4], bh[2][4], bl[2][4];
#pragma unroll
            for (int mi = 0; mi < 4; mi++) {
                int row = warp_m * 64 + mi * 16 + (lane & 15);
                int ch = s * 2 + (lane >> 4);
                LDSM4(ah[mi], st + sw_off(row, ch));
            }
#pragma unroll
            for (int bj = 0; bj < 2; bj++) {
                int nrow = warp_n * 32 + bj * 16 + ((lane >> 4) << 3) + (lane & 7);
                int ch = s * 2 + ((lane >> 3) & 1);
                uint32_t ad = st + 8192 + sw_off(nrow, ch);
                LDSM4(bh[bj], ad);
                LDSM4(bl[bj], ad + 8192);
            }
#pragma unroll
            for (int mi = 0; mi < 4; mi++)
#pragma unroll
                for (int nt = 0; nt < 4; nt++) {
                    const uint32_t* ph = bh[nt >> 1] + (nt & 1) * 2;
                    const uint32_t* pl = bl[nt >> 1] + (nt & 1) * 2;
                    MMA16816(acc[mi][nt], ah[mi], ph);
                    MMA16816(acc[mi][nt], ah[mi], pl);
                }
        }
    }

    // epilogue: + bias, fp32 out
    float2 bfrag[4];
#pragma unroll
    for (int nt = 0; nt < 4; nt++)
        bfrag[nt] = *(const float2*)(bias + n0 + warp_n * 32 + nt * 8 + (lane & 3) * 2);

#pragma unroll
    for (int mi = 0; mi < 4; mi++)
#pragma unroll
        for (int h = 0; h < 2; h++) {
            int m = m0 + warp_m * 64 + mi * 16 + (lane >> 2) + h * 8;
            float* po = out + (size_t)m * N_DIM + n0 + warp_n * 32;
#pragma unroll
            for (int nt = 0; nt < 4; nt++) {
                float2 v;
                v.x = acc[mi][nt][2 * h + 0] + bfrag[nt].x;
                v.y = acc[mi][nt][2 * h + 1] + bfrag[nt].y;
                *(float2*)(po + nt * 8 + (lane & 3) * 2) = v;
            }
        }
}

// ---------------------------------------------------------------------------
extern "C" void kernel_launch(void* const* d_in, const int* in_sizes, int n_in,
                              void* d_out, int out_size)
{
    const float* x    = (const float*)d_in[0];
    const float* mask = (const float*)d_in[1];
    const float* W    = (const float*)d_in[2];
    const float* b    = (const float*)d_in[3];
    const float* A    = (const float*)d_in[4];
    const float* Bw   = (const float*)d_in[5];
    float* out        = (float*)d_out;

    cudaFuncSetAttribute(g_gemm_kernel,
                         cudaFuncAttributeMaxDynamicSharedMemorySize, G_SMEM);
    cudaFuncSetAttribute(main_gemm_kernel,
                         cudaFuncAttributeMaxDynamicSharedMemorySize, MAIN_SMEM);

    int n4x = (M_TOTAL * K_DIM) / 4;
    conv_x_kernel<<<n4x / 256, 256>>>(x, n4x);
    int n4w = (N_DIM * K_DIM) / 4;
    split_w_kernel<<<n4w / 256, 256>>>(W, n4w);
    int n4a = (JTOT * K_DIM) / 4;
    split_a_kernel<<<(n4a + 255) / 256, 256>>>(A, n4a);
    conv_b_kernel<<<(4 * 2048 * 16) / 256, 256>>>(Bw);

    g_gemm_kernel<<<M_TOTAL / 128, 256, G_SMEM>>>(mask);

    dim3 grid(N_DIM / 128, M_TOTAL / 128);
    main_gemm_kernel<<<grid, 256, MAIN_SMEM>>>(b, out);
}

// round 5
// speedup vs baseline: 4.8034x; 1.3359x over previous
#include <cuda_runtime.h>
#include <cuda_fp16.h>
#include <cstdint>

#define M_TOTAL 16384
#define K_DIM   2048
#define N_DIM   2048
#define JTOT    64
#define SCALE_F 2.0f

// ---------------- device scratch ------------------------------------------
__device__ __align__(16) __half g_xh[(size_t)M_TOTAL * K_DIM];   // x, 1 term
__device__ __align__(16) __half g_wh[(size_t)N_DIM * K_DIM];     // W hi
__device__ __align__(16) __half g_wl[(size_t)N_DIM * K_DIM];     // W lo
__device__ __align__(16) __half g_ah[(size_t)JTOT * K_DIM];      // Acat hi
__device__ __align__(16) __half g_al[(size_t)JTOT * K_DIM];      // Acat lo
__device__ __align__(16) __half g_g [(size_t)M_TOTAL * JTOT];    // G, 1 term
__device__ __align__(16) __half g_bh[(size_t)N_DIM * JTOT];      // Bcat hi
__device__ __align__(16) __half g_bl[(size_t)N_DIM * JTOT];      // Bcat lo

// ---------------- helpers --------------------------------------------------
static __device__ __forceinline__ uint32_t smem_u32(const void* p) {
    uint32_t a;
    asm("{ .reg .u64 t; cvta.to.shared.u64 t, %1; cvt.u32.u64 %0, t; }"
        : "=r"(a) : "l"(p));
    return a;
}
static __device__ __forceinline__ uint32_t f16x2(float a, float b) {
    uint32_t r;
    asm("cvt.rn.f16x2.f32 %0, %1, %2;" : "=r"(r) : "f"(b), "f"(a));
    return r;
}
static __device__ __forceinline__ void cpasync16(uint32_t dst, const void* src) {
    asm volatile("cp.async.cg.shared.global [%0], [%1], 16;"
                 :: "r"(dst), "l"(src) : "memory");
}
#define CP_COMMIT() asm volatile("cp.async.commit_group;" ::: "memory")
#define CP_WAIT2()  asm volatile("cp.async.wait_group 2;" ::: "memory")

#define LDSM4(r, addr)                                                       \
    asm volatile("ldmatrix.sync.aligned.m8n8.x4.shared.b16 {%0,%1,%2,%3}, [%4];" \
        : "=r"((r)[0]), "=r"((r)[1]), "=r"((r)[2]), "=r"((r)[3]) : "r"(addr))

#define MMA16816(c, a, b)                                                    \
    asm volatile(                                                            \
        "mma.sync.aligned.m16n8k16.row.col.f32.f16.f16.f32 "                 \
        "{%0,%1,%2,%3}, {%4,%5,%6,%7}, {%8,%9}, {%0,%1,%2,%3};"              \
        : "+f"((c)[0]), "+f"((c)[1]), "+f"((c)[2]), "+f"((c)[3])             \
        : "r"((a)[0]), "r"((a)[1]), "r"((a)[2]), "r"((a)[3]),                \
          "r"((b)[0]), "r"((b)[1]))

// Swizzled smem offset: 64B rows (BK=32 halves), 4 chunks of 16B.
static __device__ __forceinline__ uint32_t sw_off(int row, int chunk) {
    return (uint32_t)(row * 64 + ((chunk ^ ((row >> 1) & 3)) << 4));
}

// ---------------- conversion kernels --------------------------------------
__global__ void conv_x_kernel(const float* __restrict__ src, int n4) {
    int i = blockIdx.x * blockDim.x + threadIdx.x;
    if (i >= n4) return;
    float4 v = ((const float4*)src)[i];
    uint2 h;
    h.x = f16x2(v.x, v.y);
    h.y = f16x2(v.z, v.w);
    ((uint2*)g_xh)[i] = h;
}
static __device__ __forceinline__ void split4h(float4 v, uint2& h, uint2& l) {
    __half h0 = __float2half_rn(v.x), h1 = __float2half_rn(v.y);
    __half h2 = __float2half_rn(v.z), h3 = __float2half_rn(v.w);
    h.x = ((uint32_t)__half_as_ushort(h1) << 16) | __half_as_ushort(h0);
    h.y = ((uint32_t)__half_as_ushort(h3) << 16) | __half_as_ushort(h2);
    l.x = f16x2(v.x - __half2float(h0), v.y - __half2float(h1));
    l.y = f16x2(v.z - __half2float(h2), v.w - __half2float(h3));
}
__global__ void split_w_kernel(const float* __restrict__ src, int n4) {
    int i = blockIdx.x * blockDim.x + threadIdx.x;
    if (i >= n4) return;
    float4 v = ((const float4*)src)[i];
    uint2 h, l;
    split4h(v, h, l);
    ((uint2*)g_wh)[i] = h;
    ((uint2*)g_wl)[i] = l;
}
__global__ void split_a_kernel(const float* __restrict__ src, int n4) {
    int i = blockIdx.x * blockDim.x + threadIdx.x;
    if (i >= n4) return;
    float4 v = ((const float4*)src)[i];
    uint2 h, l;
    split4h(v, h, l);
    ((uint2*)g_ah)[i] = h;
    ((uint2*)g_al)[i] = l;
}
__global__ void conv_b_kernel(const float* __restrict__ Bw) {
    int idx = blockIdx.x * blockDim.x + threadIdx.x;
    int na = idx >> 15;
    int n  = (idx >> 4) & 2047;
    int r  = idx & 15;
    float v = Bw[idx];
    __half h = __float2half_rn(v);
    __half lo = __float2half_rn(v - __half2float(h));
    size_t dst = (size_t)n * JTOT + na * 16 + r;
    g_bh[dst] = h;
    g_bl[dst] = lo;
}

// ---------------- G kernel: G = (x @ Acat^T) * SCALE * mask ---------------
#define G_STAGE  16384
#define G_SMEM   (4 * G_STAGE)

__global__ __launch_bounds__(256, 2) void g_gemm_kernel(
    const float* __restrict__ mask)
{
    extern __shared__ __align__(128) char smem[];
    const uint32_t sb = smem_u32(smem);
    const int tid = threadIdx.x, wid = tid >> 5, lane = tid & 31;
    const int warp_m = wid >> 2, warp_n = wid & 3;
    const int m0 = blockIdx.x * 128;

    float acc[4][2][4];
#pragma unroll
    for (int i = 0; i < 4; i++)
#pragma unroll
        for (int j = 0; j < 2; j++)
#pragma unroll
            for (int p = 0; p < 4; p++) acc[i][j][p] = 0.f;

    auto load_stage = [&](int c, int st_i) {
        uint32_t st = sb + (uint32_t)st_i * G_STAGE;
        const __half* px  = g_xh + (size_t)m0 * K_DIM + c * 32;
        const __half* pah = g_ah + (size_t)c * 32;
        const __half* pal = g_al + (size_t)c * 32;
#pragma unroll
        for (int q = 0; q < 2; q++) {
            int idx = tid + q * 256;
            int m = idx >> 2, ch = idx & 3;
            cpasync16(st + sw_off(m, ch), px + (size_t)m * K_DIM + ch * 8);
        }
        {
            int n = tid >> 2, ch = tid & 3;
            uint32_t so = sw_off(n, ch);
            size_t go = (size_t)n * K_DIM + ch * 8;
            cpasync16(st + 8192 + so, pah + go);
            cpasync16(st + 12288 + so, pal + go);
        }
    };

    load_stage(0, 0); CP_COMMIT();
    load_stage(1, 1); CP_COMMIT();
    load_stage(2, 2); CP_COMMIT();

    for (int c = 0; c < 64; c++) {
        CP_WAIT2();
        __syncthreads();
        if (c + 3 < 64) load_stage(c + 3, (c + 3) & 3);
        CP_COMMIT();

        uint32_t st = sb + (uint32_t)(c & 3) * G_STAGE;
#pragma unroll
        for (int s = 0; s < 2; s++) {
            uint32_t xa[4][4], bh[4], bl[4];
#pragma unroll
            for (int mi = 0; mi < 4; mi++) {
                int row = warp_m * 64 + mi * 16 + (lane & 15);
                int ch = s * 2 + (lane >> 4);
                LDSM4(xa[mi], st + sw_off(row, ch));
            }
            {
                int nrow = warp_n * 16 + ((lane >> 4) << 3) + (lane & 7);
                int ch = s * 2 + ((lane >> 3) & 1);
                uint32_t ad = st + 8192 + sw_off(nrow, ch);
                LDSM4(bh, ad);
                LDSM4(bl, ad + 4096);
            }
#pragma unroll
            for (int mi = 0; mi < 4; mi++)
#pragma unroll
                for (int nt = 0; nt < 2; nt++) {
                    MMA16816(acc[mi][nt], xa[mi], bh + nt * 2);
                    MMA16816(acc[mi][nt], xa[mi], bl + nt * 2);
                }
        }
    }

#pragma unroll
    for (int mi = 0; mi < 4; mi++)
#pragma unroll
        for (int h = 0; h < 2; h++) {
            int m = m0 + warp_m * 64 + mi * 16 + (lane >> 2) + h * 8;
            float mv = mask[(size_t)warp_n * M_TOTAL + m] * SCALE_F;
#pragma unroll
            for (int nt = 0; nt < 2; nt++) {
                float v0 = acc[mi][nt][2 * h + 0] * mv;
                float v1 = acc[mi][nt][2 * h + 1] * mv;
                size_t off = (size_t)m * JTOT + warp_n * 16 + nt * 8 + (lane & 3) * 2;
                *(uint32_t*)(g_g + off) = f16x2(v0, v1);
            }
        }
}

// ---------------- main fused GEMM -----------------------------------------
// out = x@W^T + G@Bcat^T + b.  BM=128, BN=256, BK=32, 66 K-chunks.
// Warps 2x4, warp tile 64x64.  Planes: A 8K @0, BH 16K @8192, BL 16K @24576.
#define MSTAGE 40960
#define MAIN_SMEM (4 * MSTAGE)
#define NCHUNK 66

__global__ __launch_bounds__(256, 1) void main_gemm_kernel(
    const float* __restrict__ bias, float* __restrict__ out)
{
    extern __shared__ __align__(128) char smem[];
    const uint32_t sb = smem_u32(smem);
    const int tid = threadIdx.x, wid = tid >> 5, lane = tid & 31;
    const int warp_m = wid >> 2, warp_n = wid & 3;
    const int n0 = blockIdx.x * 256, m0 = blockIdx.y * 128;

    float acc[4][8][4];
#pragma unroll
    for (int i = 0; i < 4; i++)
#pragma unroll
        for (int j = 0; j < 8; j++)
#pragma unroll
            for (int p = 0; p < 4; p++) acc[i][j][p] = 0.f;

    auto load_stage = [&](int c, int st_i) {
        uint32_t st = sb + (uint32_t)st_i * MSTAGE;
        const __half *pa, *pbh, *pbl;
        size_t strd;
        if (c < 64) {
            pa  = g_xh + (size_t)m0 * K_DIM + c * 32;
            pbh = g_wh + (size_t)n0 * K_DIM + c * 32;
            pbl = g_wl + (size_t)n0 * K_DIM + c * 32;
            strd = K_DIM;
        } else {
            pa  = g_g  + (size_t)m0 * JTOT + (c - 64) * 32;
            pbh = g_bh + (size_t)n0 * JTOT + (c - 64) * 32;
            pbl = g_bl + (size_t)n0 * JTOT + (c - 64) * 32;
            strd = JTOT;
        }
#pragma unroll
        for (int q = 0; q < 2; q++) {           // A: 128 rows x 4 chunks
            int idx = tid + q * 256;
            int r = idx >> 2, ch = idx & 3;
            cpasync16(st + sw_off(r, ch), pa + (size_t)r * strd + ch * 8);
        }
#pragma unroll
        for (int q = 0; q < 4; q++) {           // B: 256 rows x 4 chunks
            int idx = tid + q * 256;
            int r = idx >> 2, ch = idx & 3;
            uint32_t so = sw_off(r, ch);
            size_t go = (size_t)r * strd + ch * 8;
            cpasync16(st + 8192 + so, pbh + go);
            cpasync16(st + 24576 + so, pbl + go);
        }
    };

    load_stage(0, 0); CP_COMMIT();
    load_stage(1, 1); CP_COMMIT();
    load_stage(2, 2); CP_COMMIT();

    for (int c = 0; c < NCHUNK; c++) {
        CP_WAIT2();
        __syncthreads();
        if (c + 3 < NCHUNK) load_stage(c + 3, (c + 3) & 3);
        CP_COMMIT();

        uint32_t st = sb + (uint32_t)(c & 3) * MSTAGE;
#pragma unroll
        for (int s = 0; s < 2; s++) {
            uint32_t ah[4][4], bh[4][4], bl[4][4];
#pragma unroll
            for (int mi = 0; mi < 4; mi++) {
                int row = warp_m * 64 + mi * 16 + (lane & 15);
                int ch = s * 2 + (lane >> 4);
                LDSM4(ah[mi], st + sw_off(row, ch));
            }
#pragma unroll
            for (int bj = 0; bj < 4; bj++) {
                int nrow = warp_n * 64 + bj * 16 + ((lane >> 4) << 3) + (lane & 7);
                int ch = s * 2 + ((lane >> 3) & 1);
                uint32_t ad = st + 8192 + sw_off(nrow, ch);
                LDSM4(bh[bj], ad);
                LDSM4(bl[bj], ad + 16384);
            }
#pragma unroll
            for (int mi = 0; mi < 4; mi++)
#pragma unroll
                for (int nt = 0; nt < 8; nt++) {
                    const uint32_t* ph = bh[nt >> 1] + (nt & 1) * 2;
                    const uint32_t* pl = bl[nt >> 1] + (nt & 1) * 2;
                    MMA16816(acc[mi][nt], ah[mi], ph);
                    MMA16816(acc[mi][nt], ah[mi], pl);
                }
        }
    }

    // epilogue: + bias, fp32 out
    float2 bfrag[8];
#pragma unroll
    for (int nt = 0; nt < 8; nt++)
        bfrag[nt] = *(const float2*)(bias + n0 + warp_n * 64 + nt * 8 + (lane & 3) * 2);

#pragma unroll
    for (int mi = 0; mi < 4; mi++)
#pragma unroll
        for (int h = 0; h < 2; h++) {
            int m = m0 + warp_m * 64 + mi * 16 + (lane >> 2) + h * 8;
            float* po = out + (size_t)m * N_DIM + n0 + warp_n * 64;
#pragma unroll
            for (int nt = 0; nt < 8; nt++) {
                float2 v;
                v.x = acc[mi][nt][2 * h + 0] + bfrag[nt].x;
                v.y = acc[mi][nt][2 * h + 1] + bfrag[nt].y;
                *(float2*)(po + nt * 8 + (lane & 3) * 2) = v;
            }
        }
}

// ---------------------------------------------------------------------------
extern "C" void kernel_launch(void* const* d_in, const int* in_sizes, int n_in,
                              void* d_out, int out_size)
{
    const float* x    = (const float*)d_in[0];
    const float* mask = (const float*)d_in[1];
    const float* W    = (const float*)d_in[2];
    const float* b    = (const float*)d_in[3];
    const float* A    = (const float*)d_in[4];
    const float* Bw   = (const float*)d_in[5];
    float* out        = (float*)d_out;

    cudaFuncSetAttribute(g_gemm_kernel,
                         cudaFuncAttributeMaxDynamicSharedMemorySize, G_SMEM);
    cudaFuncSetAttribute(main_gemm_kernel,
                         cudaFuncAttributeMaxDynamicSharedMemorySize, MAIN_SMEM);

    int n4x = (M_TOTAL * K_DIM) / 4;
    conv_x_kernel<<<n4x / 256, 256>>>(x, n4x);
    int n4w = (N_DIM * K_DIM) / 4;
    split_w_kernel<<<n4w / 256, 256>>>(W, n4w);
    int n4a = (JTOT * K_DIM) / 4;
    split_a_kernel<<<(n4a + 255) / 256, 256>>>(A, n4a);
    conv_b_kernel<<<(4 * 2048 * 16) / 256, 256>>>(Bw);

    g_gemm_kernel<<<M_TOTAL / 128, 256, G_SMEM>>>(mask);

    dim3 grid(N_DIM / 256, M_TOTAL / 128);
    main_gemm_kernel<<<grid, 256, MAIN_SMEM>>>(b, out);
}

// round 6
// speedup vs baseline: 7.8088x; 1.6257x over previous
#include <cuda_runtime.h>
#include <cuda_fp16.h>
#include <cstdint>

#define M_TOTAL 16384
#define K_DIM   2048
#define N_DIM   2048
#define JTOT    64
#define SCALE_F 2.0f

// ---------------- device scratch ------------------------------------------
__device__ __align__(16) __half g_xh[(size_t)M_TOTAL * K_DIM];   // x fp16
__device__ __align__(16) __half g_wh[(size_t)N_DIM * K_DIM];     // W fp16
__device__ __align__(16) __half g_ah[(size_t)JTOT * K_DIM];      // Acat fp16
__device__ __align__(16) __half g_g [(size_t)M_TOTAL * JTOT];    // G fp16
__device__ __align__(16) __half g_bh[(size_t)N_DIM * JTOT];      // Bcat fp16

// ---------------- helpers --------------------------------------------------
static __device__ __forceinline__ uint32_t smem_u32(const void* p) {
    uint32_t a;
    asm("{ .reg .u64 t; cvta.to.shared.u64 t, %1; cvt.u32.u64 %0, t; }"
        : "=r"(a) : "l"(p));
    return a;
}
static __device__ __forceinline__ uint32_t f16x2(float a, float b) {
    uint32_t r;
    asm("cvt.rn.f16x2.f32 %0, %1, %2;" : "=r"(r) : "f"(b), "f"(a));
    return r;
}
static __device__ __forceinline__ void cpasync16(uint32_t dst, const void* src) {
    asm volatile("cp.async.cg.shared.global [%0], [%1], 16;"
                 :: "r"(dst), "l"(src) : "memory");
}
#define CP_COMMIT() asm volatile("cp.async.commit_group;" ::: "memory")
#define CP_WAIT2()  asm volatile("cp.async.wait_group 2;" ::: "memory")

#define LDSM4(r, addr)                                                       \
    asm volatile("ldmatrix.sync.aligned.m8n8.x4.shared.b16 {%0,%1,%2,%3}, [%4];" \
        : "=r"((r)[0]), "=r"((r)[1]), "=r"((r)[2]), "=r"((r)[3]) : "r"(addr))

#define MMA16816(c, a, b)                                                    \
    asm volatile(                                                            \
        "mma.sync.aligned.m16n8k16.row.col.f32.f16.f16.f32 "                 \
        "{%0,%1,%2,%3}, {%4,%5,%6,%7}, {%8,%9}, {%0,%1,%2,%3};"              \
        : "+f"((c)[0]), "+f"((c)[1]), "+f"((c)[2]), "+f"((c)[3])             \
        : "r"((a)[0]), "r"((a)[1]), "r"((a)[2]), "r"((a)[3]),                \
          "r"((b)[0]), "r"((b)[1]))

// Swizzled smem offset: 64B rows (BK=32 halves), 4 chunks of 16B.
static __device__ __forceinline__ uint32_t sw_off(int row, int chunk) {
    return (uint32_t)(row * 64 + ((chunk ^ ((row >> 1) & 3)) << 4));
}

// ---------------- conversion kernels (plain fp32 -> fp16 casts) -----------
static __device__ __forceinline__ uint2 cvt4(float4 v) {
    uint2 h;
    h.x = f16x2(v.x, v.y);
    h.y = f16x2(v.z, v.w);
    return h;
}
__global__ void conv_x_kernel(const float* __restrict__ src, int n4) {
    int i = blockIdx.x * blockDim.x + threadIdx.x;
    if (i >= n4) return;
    ((uint2*)g_xh)[i] = cvt4(((const float4*)src)[i]);
}
__global__ void conv_w_kernel(const float* __restrict__ src, int n4) {
    int i = blockIdx.x * blockDim.x + threadIdx.x;
    if (i >= n4) return;
    ((uint2*)g_wh)[i] = cvt4(((const float4*)src)[i]);
}
__global__ void conv_a_kernel(const float* __restrict__ src, int n4) {
    int i = blockIdx.x * blockDim.x + threadIdx.x;
    if (i >= n4) return;
    ((uint2*)g_ah)[i] = cvt4(((const float4*)src)[i]);
}
// Bcat[n, na*16+r] = Bw[na, n, r]
__global__ void conv_b_kernel(const float* __restrict__ Bw) {
    int idx = blockIdx.x * blockDim.x + threadIdx.x;
    int na = idx >> 15;
    int n  = (idx >> 4) & 2047;
    int r  = idx & 15;
    g_bh[(size_t)n * JTOT + na * 16 + r] = __float2half_rn(Bw[idx]);
}

// ---------------- G kernel: G = (x @ Acat^T) * SCALE * mask ---------------
// BM=128, BN=64, BK=32.  Planes: X 8K @0, A 4K @8192.  Stage 12K x 4.
#define G_STAGE  12288
#define G_SMEM   (4 * G_STAGE)

__global__ __launch_bounds__(256, 2) void g_gemm_kernel(
    const float* __restrict__ mask)
{
    extern __shared__ __align__(128) char smem[];
    const uint32_t sb = smem_u32(smem);
    const int tid = threadIdx.x, wid = tid >> 5, lane = tid & 31;
    const int warp_m = wid >> 2, warp_n = wid & 3;
    const int m0 = blockIdx.x * 128;

    float acc[4][2][4];
#pragma unroll
    for (int i = 0; i < 4; i++)
#pragma unroll
        for (int j = 0; j < 2; j++)
#pragma unroll
            for (int p = 0; p < 4; p++) acc[i][j][p] = 0.f;

    auto load_stage = [&](int c, int st_i) {
        uint32_t st = sb + (uint32_t)st_i * G_STAGE;
        const __half* px  = g_xh + (size_t)m0 * K_DIM + c * 32;
        const __half* pah = g_ah + (size_t)c * 32;
#pragma unroll
        for (int q = 0; q < 2; q++) {
            int idx = tid + q * 256;
            int m = idx >> 2, ch = idx & 3;
            cpasync16(st + sw_off(m, ch), px + (size_t)m * K_DIM + ch * 8);
        }
        if (tid < 256) {
            int n = tid >> 2, ch = tid & 3;
            cpasync16(st + 8192 + sw_off(n, ch), pah + (size_t)n * K_DIM + ch * 8);
        }
    };

    load_stage(0, 0); CP_COMMIT();
    load_stage(1, 1); CP_COMMIT();
    load_stage(2, 2); CP_COMMIT();

    for (int c = 0; c < 64; c++) {
        CP_WAIT2();
        __syncthreads();
        if (c + 3 < 64) load_stage(c + 3, (c + 3) & 3);
        CP_COMMIT();

        uint32_t st = sb + (uint32_t)(c & 3) * G_STAGE;
#pragma unroll
        for (int s = 0; s < 2; s++) {
            uint32_t xa[4][4], bh[4];
#pragma unroll
            for (int mi = 0; mi < 4; mi++) {
                int row = warp_m * 64 + mi * 16 + (lane & 15);
                int ch = s * 2 + (lane >> 4);
                LDSM4(xa[mi], st + sw_off(row, ch));
            }
            {
                int nrow = warp_n * 16 + ((lane >> 4) << 3) + (lane & 7);
                int ch = s * 2 + ((lane >> 3) & 1);
                LDSM4(bh, st + 8192 + sw_off(nrow, ch));
            }
#pragma unroll
            for (int mi = 0; mi < 4; mi++)
#pragma unroll
                for (int nt = 0; nt < 2; nt++)
                    MMA16816(acc[mi][nt], xa[mi], bh + nt * 2);
        }
    }

#pragma unroll
    for (int mi = 0; mi < 4; mi++)
#pragma unroll
        for (int h = 0; h < 2; h++) {
            int m = m0 + warp_m * 64 + mi * 16 + (lane >> 2) + h * 8;
            float mv = mask[(size_t)warp_n * M_TOTAL + m] * SCALE_F;
#pragma unroll
            for (int nt = 0; nt < 2; nt++) {
                float v0 = acc[mi][nt][2 * h + 0] * mv;
                float v1 = acc[mi][nt][2 * h + 1] * mv;
                size_t off = (size_t)m * JTOT + warp_n * 16 + nt * 8 + (lane & 3) * 2;
                *(uint32_t*)(g_g + off) = f16x2(v0, v1);
            }
        }
}

// ---------------- main fused GEMM -----------------------------------------
// out = x@W^T + G@Bcat^T + b.  BM=128, BN=256, BK=32, 66 K-chunks.
// Warps 2x4, warp tile 64x64.  Planes: A 8K @0, B 16K @8192.  Stage 24K x 4.
#define MSTAGE 24576
#define MAIN_SMEM (4 * MSTAGE)
#define NCHUNK 66

__global__ __launch_bounds__(256, 1) void main_gemm_kernel(
    const float* __restrict__ bias, float* __restrict__ out)
{
    extern __shared__ __align__(128) char smem[];
    const uint32_t sb = smem_u32(smem);
    const int tid = threadIdx.x, wid = tid >> 5, lane = tid & 31;
    const int warp_m = wid >> 2, warp_n = wid & 3;
    const int n0 = blockIdx.x * 256, m0 = blockIdx.y * 128;

    float acc[4][8][4];
#pragma unroll
    for (int i = 0; i < 4; i++)
#pragma unroll
        for (int j = 0; j < 8; j++)
#pragma unroll
            for (int p = 0; p < 4; p++) acc[i][j][p] = 0.f;

    auto load_stage = [&](int c, int st_i) {
        uint32_t st = sb + (uint32_t)st_i * MSTAGE;
        const __half *pa, *pb;
        size_t strd;
        if (c < 64) {
            pa = g_xh + (size_t)m0 * K_DIM + c * 32;
            pb = g_wh + (size_t)n0 * K_DIM + c * 32;
            strd = K_DIM;
        } else {
            pa = g_g  + (size_t)m0 * JTOT + (c - 64) * 32;
            pb = g_bh + (size_t)n0 * JTOT + (c - 64) * 32;
            strd = JTOT;
        }
#pragma unroll
        for (int q = 0; q < 2; q++) {           // A: 128 rows x 4 chunks
            int idx = tid + q * 256;
            int r = idx >> 2, ch = idx & 3;
            cpasync16(st + sw_off(r, ch), pa + (size_t)r * strd + ch * 8);
        }
#pragma unroll
        for (int q = 0; q < 4; q++) {           // B: 256 rows x 4 chunks
            int idx = tid + q * 256;
            int r = idx >> 2, ch = idx & 3;
            cpasync16(st + 8192 + sw_off(r, ch), pb + (size_t)r * strd + ch * 8);
        }
    };

    load_stage(0, 0); CP_COMMIT();
    load_stage(1, 1); CP_COMMIT();
    load_stage(2, 2); CP_COMMIT();

    for (int c = 0; c < NCHUNK; c++) {
        CP_WAIT2();
        __syncthreads();
        if (c + 3 < NCHUNK) load_stage(c + 3, (c + 3) & 3);
        CP_COMMIT();

        uint32_t st = sb + (uint32_t)(c & 3) * MSTAGE;
#pragma unroll
        for (int s = 0; s < 2; s++) {
            uint32_t ah[4][4], bh[4][4];
#pragma unroll
            for (int mi = 0; mi < 4; mi++) {
                int row = warp_m * 64 + mi * 16 + (lane & 15);
                int ch = s * 2 + (lane >> 4);
                LDSM4(ah[mi], st + sw_off(row, ch));
            }
#pragma unroll
            for (int bj = 0; bj < 4; bj++) {
                int nrow = warp_n * 64 + bj * 16 + ((lane >> 4) << 3) + (lane & 7);
                int ch = s * 2 + ((lane >> 3) & 1);
                LDSM4(bh[bj], st + 8192 + sw_off(nrow, ch));
            }
#pragma unroll
            for (int mi = 0; mi < 4; mi++)
#pragma unroll
                for (int nt = 0; nt < 8; nt++)
                    MMA16816(acc[mi][nt], ah[mi], bh[nt >> 1] + (nt & 1) * 2);
        }
    }

    // epilogue: + bias, fp32 out
    float2 bfrag[8];
#pragma unroll
    for (int nt = 0; nt < 8; nt++)
        bfrag[nt] = *(const float2*)(bias + n0 + warp_n * 64 + nt * 8 + (lane & 3) * 2);

#pragma unroll
    for (int mi = 0; mi < 4; mi++)
#pragma unroll
        for (int h = 0; h < 2; h++) {
            int m = m0 + warp_m * 64 + mi * 16 + (lane >> 2) + h * 8;
            float* po = out + (size_t)m * N_DIM + n0 + warp_n * 64;
#pragma unroll
            for (int nt = 0; nt < 8; nt++) {
                float2 v;
                v.x = acc[mi][nt][2 * h + 0] + bfrag[nt].x;
                v.y = acc[mi][nt][2 * h + 1] + bfrag[nt].y;
                *(float2*)(po + nt * 8 + (lane & 3) * 2) = v;
            }
        }
}

// ---------------------------------------------------------------------------
extern "C" void kernel_launch(void* const* d_in, const int* in_sizes, int n_in,
                              void* d_out, int out_size)
{
    const float* x    = (const float*)d_in[0];
    const float* mask = (const float*)d_in[1];
    const float* W    = (const float*)d_in[2];
    const float* b    = (const float*)d_in[3];
    const float* A    = (const float*)d_in[4];
    const float* Bw   = (const float*)d_in[5];
    float* out        = (float*)d_out;

    cudaFuncSetAttribute(g_gemm_kernel,
                         cudaFuncAttributeMaxDynamicSharedMemorySize, G_SMEM);
    cudaFuncSetAttribute(main_gemm_kernel,
                         cudaFuncAttributeMaxDynamicSharedMemorySize, MAIN_SMEM);

    int n4x = (M_TOTAL * K_DIM) / 4;
    conv_x_kernel<<<n4x / 256, 256>>>(x, n4x);
    int n4w = (N_DIM * K_DIM) / 4;
    conv_w_kernel<<<n4w / 256, 256>>>(W, n4w);
    int n4a = (JTOT * K_DIM) / 4;
    conv_a_kernel<<<(n4a + 255) / 256, 256>>>(A, n4a);
    conv_b_kernel<<<(4 * 2048 * 16) / 256, 256>>>(Bw);

    g_gemm_kernel<<<M_TOTAL / 128, 256, G_SMEM>>>(mask);

    dim3 grid(N_DIM / 256, M_TOTAL / 128);
    main_gemm_kernel<<<grid, 256, MAIN_SMEM>>>(b, out);
}

// round 7
// speedup vs baseline: 8.9932x; 1.1517x over previous
#include <cuda_runtime.h>
#include <cuda_fp16.h>
#include <cstdint>

#define M_TOTAL 16384
#define K_DIM   2048
#define N_DIM   2048
#define JTOT    64
#define SCALE_F 2.0f

// ---------------- device scratch ------------------------------------------
__device__ __align__(16) __half g_xh[(size_t)M_TOTAL * K_DIM];   // x fp16
__device__ __align__(16) __half g_wh[(size_t)N_DIM * K_DIM];     // W fp16
__device__ __align__(16) __half g_ah[(size_t)JTOT * K_DIM];      // Acat fp16
__device__ __align__(16) __half g_g [(size_t)M_TOTAL * JTOT];    // G fp16
__device__ __align__(16) __half g_bh[(size_t)N_DIM * JTOT];      // Bcat fp16

// ---------------- helpers --------------------------------------------------
static __device__ __forceinline__ uint32_t smem_u32(const void* p) {
    uint32_t a;
    asm("{ .reg .u64 t; cvta.to.shared.u64 t, %1; cvt.u32.u64 %0, t; }"
        : "=r"(a) : "l"(p));
    return a;
}
static __device__ __forceinline__ uint32_t f16x2(float a, float b) {
    uint32_t r;
    asm("cvt.rn.f16x2.f32 %0, %1, %2;" : "=r"(r) : "f"(b), "f"(a));
    return r;
}
static __device__ __forceinline__ void cpasync16(uint32_t dst, const void* src) {
    asm volatile("cp.async.cg.shared.global [%0], [%1], 16;"
                 :: "r"(dst), "l"(src) : "memory");
}
#define CP_COMMIT() asm volatile("cp.async.commit_group;" ::: "memory")
#define CP_WAIT1()  asm volatile("cp.async.wait_group 1;" ::: "memory")
#define CP_WAIT2()  asm volatile("cp.async.wait_group 2;" ::: "memory")

#define LDSM4(r, addr)                                                       \
    asm volatile("ldmatrix.sync.aligned.m8n8.x4.shared.b16 {%0,%1,%2,%3}, [%4];" \
        : "=r"((r)[0]), "=r"((r)[1]), "=r"((r)[2]), "=r"((r)[3]) : "r"(addr))

#define MMA16816(c, a, b)                                                    \
    asm volatile(                                                            \
        "mma.sync.aligned.m16n8k16.row.col.f32.f16.f16.f32 "                 \
        "{%0,%1,%2,%3}, {%4,%5,%6,%7}, {%8,%9}, {%0,%1,%2,%3};"              \
        : "+f"((c)[0]), "+f"((c)[1]), "+f"((c)[2]), "+f"((c)[3])             \
        : "r"((a)[0]), "r"((a)[1]), "r"((a)[2]), "r"((a)[3]),                \
          "r"((b)[0]), "r"((b)[1]))

// 64B-row swizzle (BK=32 tiles, G kernel)
static __device__ __forceinline__ uint32_t sw_off(int row, int chunk) {
    return (uint32_t)(row * 64 + ((chunk ^ ((row >> 1) & 3)) << 4));
}
// 128B-row SW128 swizzle (BK=64 tiles, main kernel)
static __device__ __forceinline__ uint32_t sw128(int row, int chunk) {
    return (uint32_t)(row * 128 + ((chunk ^ (row & 7)) << 4));
}

// ---------------- conversion kernels --------------------------------------
static __device__ __forceinline__ uint2 cvt4(float4 v) {
    uint2 h;
    h.x = f16x2(v.x, v.y);
    h.y = f16x2(v.z, v.w);
    return h;
}
__global__ void conv_x_kernel(const float* __restrict__ src, int n4) {
    int i = blockIdx.x * blockDim.x + threadIdx.x;
    if (i >= n4) return;
    ((uint2*)g_xh)[i] = cvt4(((const float4*)src)[i]);
}
__global__ void conv_w_kernel(const float* __restrict__ src, int n4) {
    int i = blockIdx.x * blockDim.x + threadIdx.x;
    if (i >= n4) return;
    ((uint2*)g_wh)[i] = cvt4(((const float4*)src)[i]);
}
__global__ void conv_a_kernel(const float* __restrict__ src, int n4) {
    int i = blockIdx.x * blockDim.x + threadIdx.x;
    if (i >= n4) return;
    ((uint2*)g_ah)[i] = cvt4(((const float4*)src)[i]);
}
__global__ void conv_b_kernel(const float* __restrict__ Bw) {
    int idx = blockIdx.x * blockDim.x + threadIdx.x;
    int na = idx >> 15;
    int n  = (idx >> 4) & 2047;
    int r  = idx & 15;
    g_bh[(size_t)n * JTOT + na * 16 + r] = __float2half_rn(Bw[idx]);
}

// ---------------- G kernel: G = (x @ Acat^T) * SCALE * mask ---------------
#define G_STAGE  12288
#define G_SMEM   (4 * G_STAGE)

__global__ __launch_bounds__(256, 2) void g_gemm_kernel(
    const float* __restrict__ mask)
{
    extern __shared__ __align__(128) char smem[];
    const uint32_t sb = smem_u32(smem);
    const int tid = threadIdx.x, wid = tid >> 5, lane = tid & 31;
    const int warp_m = wid >> 2, warp_n = wid & 3;
    const int m0 = blockIdx.x * 128;

    float acc[4][2][4];
#pragma unroll
    for (int i = 0; i < 4; i++)
#pragma unroll
        for (int j = 0; j < 2; j++)
#pragma unroll
            for (int p = 0; p < 4; p++) acc[i][j][p] = 0.f;

    auto load_stage = [&](int c, int st_i) {
        uint32_t st = sb + (uint32_t)st_i * G_STAGE;
        const __half* px  = g_xh + (size_t)m0 * K_DIM + c * 32;
        const __half* pah = g_ah + (size_t)c * 32;
#pragma unroll
        for (int q = 0; q < 2; q++) {
            int idx = tid + q * 256;
            int m = idx >> 2, ch = idx & 3;
            cpasync16(st + sw_off(m, ch), px + (size_t)m * K_DIM + ch * 8);
        }
        {
            int n = tid >> 2, ch = tid & 3;
            cpasync16(st + 8192 + sw_off(n, ch), pah + (size_t)n * K_DIM + ch * 8);
        }
    };

    load_stage(0, 0); CP_COMMIT();
    load_stage(1, 1); CP_COMMIT();
    load_stage(2, 2); CP_COMMIT();

    for (int c = 0; c < 64; c++) {
        CP_WAIT2();
        __syncthreads();
        if (c + 3 < 64) load_stage(c + 3, (c + 3) & 3);
        CP_COMMIT();

        uint32_t st = sb + (uint32_t)(c & 3) * G_STAGE;
#pragma unroll
        for (int s = 0; s < 2; s++) {
            uint32_t xa[4][4], bh[4];
#pragma unroll
            for (int mi = 0; mi < 4; mi++) {
                int row = warp_m * 64 + mi * 16 + (lane & 15);
                int ch = s * 2 + (lane >> 4);
                LDSM4(xa[mi], st + sw_off(row, ch));
            }
            {
                int nrow = warp_n * 16 + ((lane >> 4) << 3) + (lane & 7);
                int ch = s * 2 + ((lane >> 3) & 1);
                LDSM4(bh, st + 8192 + sw_off(nrow, ch));
            }
#pragma unroll
            for (int mi = 0; mi < 4; mi++)
#pragma unroll
                for (int nt = 0; nt < 2; nt++)
                    MMA16816(acc[mi][nt], xa[mi], bh + nt * 2);
        }
    }

#pragma unroll
    for (int mi = 0; mi < 4; mi++)
#pragma unroll
        for (int h = 0; h < 2; h++) {
            int m = m0 + warp_m * 64 + mi * 16 + (lane >> 2) + h * 8;
            float mv = mask[(size_t)warp_n * M_TOTAL + m] * SCALE_F;
#pragma unroll
            for (int nt = 0; nt < 2; nt++) {
                float v0 = acc[mi][nt][2 * h + 0] * mv;
                float v1 = acc[mi][nt][2 * h + 1] * mv;
                size_t off = (size_t)m * JTOT + warp_n * 16 + nt * 8 + (lane & 3) * 2;
                *(uint32_t*)(g_g + off) = f16x2(v0, v1);
            }
        }
}

// ---------------- main fused GEMM -----------------------------------------
// out = x@W^T + G@Bcat^T + b.  BM=128, BN=256, BK=64, 33 chunks (32 + LoRA).
// Warps 2x4, warp tile 64x64.  Planes: A 16K @0, B 32K @16384.  Stage 48K x3.
#define MSTAGE 49152
#define MAIN_SMEM (3 * MSTAGE)
#define NCHUNK 33

__global__ __launch_bounds__(256, 1) void main_gemm_kernel(
    const float* __restrict__ bias, float* __restrict__ out)
{
    extern __shared__ __align__(128) char smem[];
    const uint32_t sb = smem_u32(smem);
    const int tid = threadIdx.x, wid = tid >> 5, lane = tid & 31;
    const int warp_m = wid >> 2, warp_n = wid & 3;
    const int n0 = blockIdx.x * 256, m0 = blockIdx.y * 128;

    float acc[4][8][4];
#pragma unroll
    for (int i = 0; i < 4; i++)
#pragma unroll
        for (int j = 0; j < 8; j++)
#pragma unroll
            for (int p = 0; p < 4; p++) acc[i][j][p] = 0.f;

    auto load_stage = [&](int c, int st_i) {
        uint32_t st = sb + (uint32_t)st_i * MSTAGE;
        const __half *pa, *pb;
        size_t strd;
        if (c < 32) {
            pa = g_xh + (size_t)m0 * K_DIM + c * 64;
            pb = g_wh + (size_t)n0 * K_DIM + c * 64;
            strd = K_DIM;
        } else {
            pa = g_g  + (size_t)m0 * JTOT;
            pb = g_bh + (size_t)n0 * JTOT;
            strd = JTOT;
        }
#pragma unroll
        for (int q = 0; q < 4; q++) {           // A: 128 rows x 8 chunks
            int idx = tid + q * 256;
            int r = idx >> 3, ch = idx & 7;
            cpasync16(st + sw128(r, ch), pa + (size_t)r * strd + ch * 8);
        }
#pragma unroll
        for (int q = 0; q < 8; q++) {           // B: 256 rows x 8 chunks
            int idx = tid + q * 256;
            int r = idx >> 3, ch = idx & 7;
            cpasync16(st + 16384 + sw128(r, ch), pb + (size_t)r * strd + ch * 8);
        }
    };

    load_stage(0, 0); CP_COMMIT();
    load_stage(1, 1); CP_COMMIT();

    uint32_t ah[2][4][4], bh[2][4][4];

    auto load_frags = [&](uint32_t st, int s, int buf) {
#pragma unroll
        for (int mi = 0; mi < 4; mi++) {
            int row = warp_m * 64 + mi * 16 + (lane & 15);
            int ch = s * 2 + (lane >> 4);
            LDSM4(ah[buf][mi], st + sw128(row, ch));
        }
#pragma unroll
        for (int bj = 0; bj < 4; bj++) {
            int nrow = warp_n * 64 + bj * 16 + ((lane >> 4) << 3) + (lane & 7);
            int ch = s * 2 + ((lane >> 3) & 1);
            LDSM4(bh[buf][bj], st + 16384 + sw128(nrow, ch));
        }
    };

    for (int c = 0; c < NCHUNK; c++) {
        CP_WAIT1();
        __syncthreads();
        if (c + 2 < NCHUNK) load_stage(c + 2, (c + 2) % 3);
        CP_COMMIT();

        uint32_t st = sb + (uint32_t)(c % 3) * MSTAGE;
        load_frags(st, 0, 0);
#pragma unroll
        for (int s = 0; s < 4; s++) {
            int cur = s & 1;
            if (s < 3) load_frags(st, s + 1, cur ^ 1);
#pragma unroll
            for (int mi = 0; mi < 4; mi++)
#pragma unroll
                for (int nt = 0; nt < 8; nt++)
                    MMA16816(acc[mi][nt], ah[cur][mi],
                             bh[cur][nt >> 1] + (nt & 1) * 2);
        }
    }

    // epilogue: + bias, fp32 out
    float2 bfrag[8];
#pragma unroll
    for (int nt = 0; nt < 8; nt++)
        bfrag[nt] = *(const float2*)(bias + n0 + warp_n * 64 + nt * 8 + (lane & 3) * 2);

#pragma unroll
    for (int mi = 0; mi < 4; mi++)
#pragma unroll
        for (int h = 0; h < 2; h++) {
            int m = m0 + warp_m * 64 + mi * 16 + (lane >> 2) + h * 8;
            float* po = out + (size_t)m * N_DIM + n0 + warp_n * 64;
#pragma unroll
            for (int nt = 0; nt < 8; nt++) {
                float2 v;
                v.x = acc[mi][nt][2 * h + 0] + bfrag[nt].x;
                v.y = acc[mi][nt][2 * h + 1] + bfrag[nt].y;
                *(float2*)(po + nt * 8 + (lane & 3) * 2) = v;
            }
        }
}

// ---------------------------------------------------------------------------
extern "C" void kernel_launch(void* const* d_in, const int* in_sizes, int n_in,
                              void* d_out, int out_size)
{
    const float* x    = (const float*)d_in[0];
    const float* mask = (const float*)d_in[1];
    const float* W    = (const float*)d_in[2];
    const float* b    = (const float*)d_in[3];
    const float* A    = (const float*)d_in[4];
    const float* Bw   = (const float*)d_in[5];
    float* out        = (float*)d_out;

    cudaFuncSetAttribute(g_gemm_kernel,
                         cudaFuncAttributeMaxDynamicSharedMemorySize, G_SMEM);
    cudaFuncSetAttribute(main_gemm_kernel,
                         cudaFuncAttributeMaxDynamicSharedMemorySize, MAIN_SMEM);

    int n4x = (M_TOTAL * K_DIM) / 4;
    conv_x_kernel<<<n4x / 256, 256>>>(x, n4x);
    int n4w = (N_DIM * K_DIM) / 4;
    conv_w_kernel<<<n4w / 256, 256>>>(W, n4w);
    int n4a = (JTOT * K_DIM) / 4;
    conv_a_kernel<<<(n4a + 255) / 256, 256>>>(A, n4a);
    conv_b_kernel<<<(4 * 2048 * 16) / 256, 256>>>(Bw);

    g_gemm_kernel<<<M_TOTAL / 128, 256, G_SMEM>>>(mask);

    dim3 grid(N_DIM / 256, M_TOTAL / 128);
    main_gemm_kernel<<<grid, 256, MAIN_SMEM>>>(b, out);
}